// round 6
// baseline (speedup 1.0000x reference)
#include <cuda_runtime.h>
#include <cstdint>
#include <math.h>

#define NT 1024
#define NH 1024
#define NF 4096
#define NE 8
#define NK 2

// ---- device scratch ----
__device__ int   g_sel [NT*NK];
__device__ float g_rw  [NT*NK];
__device__ int   g_slot[NT*NK];
__device__ int   g_cnt [NE];
__device__ int   g_off [NE];
__device__ int   g_tok [NT*NK];
__device__ float g_h[(size_t)(NT*NK)*NF];
__device__ float g_y[2][(size_t)(NT*NK)*NH];

// ---- helpers ----
__device__ __forceinline__ uint32_t smem_u32(const void* p){
    uint32_t a; asm("{ .reg .u64 t; cvta.to.shared.u64 t, %1; cvt.u32.u64 %0, t; }":"=r"(a):"l"(p)); return a;
}
__device__ __forceinline__ void cpa16(uint32_t s, const void* g){
    asm volatile("cp.async.cg.shared.global [%0], [%1], 16;"::"r"(s),"l"(g));
}
__device__ __forceinline__ void cpa_commit(){ asm volatile("cp.async.commit_group;"); }
template<int N> __device__ __forceinline__ void cpa_wait(){ asm volatile("cp.async.wait_group %0;"::"n"(N)); }
__device__ __forceinline__ uint32_t f2tf(float f){
    uint32_t r; asm("cvt.rna.tf32.f32 %0, %1;":"=r"(r):"f"(f)); return r;
}
__device__ __forceinline__ void mma8(float* d, const uint32_t* a, const uint32_t* b){
    asm volatile("mma.sync.aligned.m16n8k8.row.col.f32.tf32.tf32.f32 "
        "{%0,%1,%2,%3}, {%4,%5,%6,%7}, {%8,%9}, {%0,%1,%2,%3};"
        : "+f"(d[0]),"+f"(d[1]),"+f"(d[2]),"+f"(d[3])
        : "r"(a[0]),"r"(a[1]),"r"(a[2]),"r"(a[3]),"r"(b[0]),"r"(b[1]));
}
__device__ __forceinline__ float gelu_exact(float v){
    return 0.5f * v * (1.0f + erff(v * 0.70710678118654752f));
}

// ---- aux kernels ----
__global__ void init_kernel(){
    int i = threadIdx.x;
    if (i < NE) g_cnt[i] = 0;
}

__global__ void router_kernel(const float* __restrict__ x,
                              const float* __restrict__ gw,
                              const float* __restrict__ gb){
    __shared__ float4 sg[NE*NH/4];
    int tid = threadIdx.x;
    for (int i = tid; i < NE*NH/4; i += blockDim.x) sg[i] = ((const float4*)gw)[i];
    __syncthreads();
    int t = blockIdx.x*blockDim.x + tid;
    const float4* xr = (const float4*)(x + (size_t)t*NH);
    float acc[NE];
#pragma unroll
    for (int e=0;e<NE;e++) acc[e] = gb[e];
    for (int i=0;i<NH/4;i++){
        float4 xv = xr[i];
#pragma unroll
        for (int e=0;e<NE;e++){
            float4 g = sg[e*(NH/4)+i];
            acc[e] += xv.x*g.x + xv.y*g.y + xv.z*g.z + xv.w*g.w;
        }
    }
    int i0=0; float l0=acc[0];
#pragma unroll
    for (int e=1;e<NE;e++) if (acc[e]>l0){ l0=acc[e]; i0=e; }
    int i1=-1; float l1=-3.4e38f;
#pragma unroll
    for (int e=0;e<NE;e++) if (e!=i0 && acc[e]>l1){ l1=acc[e]; i1=e; }
    float p0 = 1.0f/(1.0f+expf(l1-l0));
    g_sel[t*2+0]=i0; g_sel[t*2+1]=i1;
    g_rw [t*2+0]=p0; g_rw [t*2+1]=1.0f-p0;
    atomicAdd(&g_cnt[i0],1);
    atomicAdd(&g_cnt[i1],1);
}

__global__ void scanfill_kernel(){
    __shared__ int scur[NE];
    int tid = threadIdx.x;
    if (tid == 0){
        int o = 0;
        for (int e=0;e<NE;e++){ g_off[e]=o; scur[e]=0; o += g_cnt[e]; }
    }
    __syncthreads();
    for (int t = tid; t < NT; t += blockDim.x){
        for (int k=0;k<NK;k++){
            int e = g_sel[t*2+k];
            int pos = atomicAdd(&scur[e],1);
            int idx = g_off[e]+pos;
            g_tok[idx]    = t;
            g_slot[t*2+k] = idx;
        }
    }
}

// ---- grouped tf32 mma.sync GEMM ----
// CTA tile 128x128, BK=32, 256 threads = 8 warps (4m x 2n), warp tile 32x64.
// Single-buffered fragments, 3-stage cp.async pipeline, 2 CTAs/SM (16 warps).
// MODE 1: g_h[slot] = gelu(x[tok] @ w1[e] + b1[e])   K=1024, ldB=NF
// MODE 2: g_y[ks][slot] = g_h[slot] @ w2[e] (splitK2) K=2048, ldB=NH

#define ASTR 36
#define BSTR 132
#define STG_A (128*ASTR)            // 4608 floats
#define STG_B (32*BSTR)             // 4224 floats
#define STG_F (STG_A + STG_B)       // 8832 floats
#define NSTG  3
#define SMEM_SZ (NSTG*STG_F*4)      // 105984 bytes

template<int MODE>
__global__ __launch_bounds__(256, 2)
void moe_gemm(const float* __restrict__ Asrc,
              const float* __restrict__ W,
              const float* __restrict__ bias){
    const int z   = blockIdx.z;
    const int e   = (MODE==1) ? z : (z & 7);
    const int ks  = (MODE==1) ? 0 : (z >> 3);
    const int cnt = g_cnt[e];
    const int m0  = blockIdx.y * 128;
    if (m0 >= cnt) return;
    const int off = g_off[e];
    const int n0  = blockIdx.x * 128;
    const int ldB = (MODE==1) ? NF : NH;
    const int Kfull = (MODE==1) ? NH : NF;
    const int Kloc  = (MODE==1) ? NH : NF/2;
    const int k0    = (MODE==1) ? 0  : ks * (NF/2);
    const int KT    = Kloc / 32;

    extern __shared__ float smem[];
    const uint32_t sb = smem_u32(smem);
    const int tid = threadIdx.x, wid = tid>>5, lane = tid&31;
    const int g = lane>>2, tg = lane&3;
    const int wm = wid&3, wn = wid>>2;   // 4m x 2n warps, warp tile 32x64

    // A loads: thread -> row tid>>1, cols (tid&1)*16 + j*4 (j=0..3)
    const int arow_l = tid>>1;
    const int acol   = (tid&1)*16;
    int mi = m0 + arow_l;
    int ci = (mi < cnt) ? mi : (cnt-1);
    const float* aptr;
    if (MODE==1) aptr = Asrc + (size_t)g_tok[off+ci]*NH + acol;
    else         aptr = Asrc + (size_t)(off+ci)*NF + k0 + acol;

    // B loads: thread -> row tid>>3, cols (tid&7)*4 + j*32 (j=0..3)
    const int brow = tid>>3;
    const int bcol = (tid&7)*4;
    const float* bptr = W + (size_t)e*Kfull*ldB + (size_t)(k0 + brow)*ldB + n0 + bcol;

    const uint32_t adst = sb + ((uint32_t)(arow_l*ASTR + acol))*4u;
    const uint32_t bdst = sb + ((uint32_t)(STG_A + brow*BSTR + bcol))*4u;

    auto load_stage = [&](int s, int kt){
        uint32_t ab = adst + (uint32_t)s*STG_F*4u;
        uint32_t bb = bdst + (uint32_t)s*STG_F*4u;
        const float* ga  = aptr + kt*32;
        const float* gbp = bptr + (size_t)kt*32*ldB;
#pragma unroll
        for (int j=0;j<4;j++) cpa16(ab + j*16u, ga + j*4);
#pragma unroll
        for (int j=0;j<4;j++) cpa16(bb + j*128u, gbp + j*32);
    };

    load_stage(0,0); cpa_commit();
    load_stage(1,1); cpa_commit();

    float acc[2][8][4];
#pragma unroll
    for (int i=0;i<2;i++)
#pragma unroll
        for (int j=0;j<8;j++)
#pragma unroll
            for (int r=0;r<4;r++) acc[i][j][r] = 0.0f;

    for (int kt = 0; kt < KT; kt++){
        cpa_wait<1>();
        __syncthreads();
        if (kt + 2 < KT) load_stage((kt+2)%NSTG, kt+2);
        cpa_commit();

        const float* sA = smem + (kt%NSTG)*STG_F;
        const float* sB = sA + STG_A;
#pragma unroll
        for (int kstep=0;kstep<4;kstep++){
            uint32_t af[2][4];
#pragma unroll
            for (int i=0;i<2;i++){
                const float* pa = sA + (wm*32 + i*16 + g)*ASTR + kstep*8 + tg;
                af[i][0] = f2tf(pa[0]);
                af[i][1] = f2tf(pa[8*ASTR]);
                af[i][2] = f2tf(pa[4]);
                af[i][3] = f2tf(pa[8*ASTR+4]);
            }
            uint32_t bf[8][2];
#pragma unroll
            for (int j=0;j<8;j++){
                const float* pb = sB + (kstep*8 + tg)*BSTR + wn*64 + j*8 + g;
                bf[j][0] = f2tf(pb[0]);
                bf[j][1] = f2tf(pb[4*BSTR]);
            }
#pragma unroll
            for (int i=0;i<2;i++)
#pragma unroll
                for (int j=0;j<8;j++)
                    mma8(acc[i][j], af[i], bf[j]);
        }
        __syncthreads();
    }

    // ---- epilogue ----
    if (MODE == 1){
        const float* bp = bias + (size_t)e*NF + n0 + wn*64;
#pragma unroll
        for (int i=0;i<2;i++){
            int r0 = m0 + wm*32 + i*16 + g;
            int r1 = r0 + 8;
#pragma unroll
            for (int j=0;j<8;j++){
                int c = j*8 + tg*2;
                float b0 = __ldg(bp + c), b1v = __ldg(bp + c + 1);
                if (r0 < cnt){
                    float* o = g_h + (size_t)(off+r0)*NF + n0 + wn*64 + c;
                    float2 v; v.x = gelu_exact(acc[i][j][0] + b0);
                              v.y = gelu_exact(acc[i][j][1] + b1v);
                    *(float2*)o = v;
                }
                if (r1 < cnt){
                    float* o = g_h + (size_t)(off+r1)*NF + n0 + wn*64 + c;
                    float2 v; v.x = gelu_exact(acc[i][j][2] + b0);
                              v.y = gelu_exact(acc[i][j][3] + b1v);
                    *(float2*)o = v;
                }
            }
        }
    } else {
        float* Yb = g_y[ks];
#pragma unroll
        for (int i=0;i<2;i++){
            int r0 = m0 + wm*32 + i*16 + g;
            int r1 = r0 + 8;
#pragma unroll
            for (int j=0;j<8;j++){
                int c = n0 + wn*64 + j*8 + tg*2;
                if (r0 < cnt)
                    *(float2*)(Yb + (size_t)(off+r0)*NH + c) = make_float2(acc[i][j][0], acc[i][j][1]);
                if (r1 < cnt)
                    *(float2*)(Yb + (size_t)(off+r1)*NH + c) = make_float2(acc[i][j][2], acc[i][j][3]);
            }
        }
    }
}

// ---- combine ----
__global__ void combine_kernel(const float* __restrict__ b2, float* __restrict__ out){
    int idx = blockIdx.x*blockDim.x + threadIdx.x;
    int t  = idx >> 8;
    int h4 = (idx & 255) * 4;
    float4 a = make_float4(0.f,0.f,0.f,0.f);
#pragma unroll
    for (int k=0;k<2;k++){
        int e = g_sel[t*2+k];
        float w = g_rw[t*2+k];
        int sl = g_slot[t*2+k];
        float4 y0 = *(const float4*)&g_y[0][(size_t)sl*NH + h4];
        float4 y1 = *(const float4*)&g_y[1][(size_t)sl*NH + h4];
        float4 bb = *(const float4*)&b2[(size_t)e*NH + h4];
        a.x += w*(y0.x+y1.x+bb.x);
        a.y += w*(y0.y+y1.y+bb.y);
        a.z += w*(y0.z+y1.z+bb.z);
        a.w += w*(y0.w+y1.w+bb.w);
    }
    *(float4*)&out[(size_t)t*NH + h4] = a;
}

extern "C" void kernel_launch(void* const* d_in, const int* in_sizes, int n_in,
                              void* d_out, int out_size){
    const float* x  = (const float*)d_in[0];
    const float* gw = (const float*)d_in[1];
    const float* gb = (const float*)d_in[2];
    const float* w1 = (const float*)d_in[3];
    const float* b1 = (const float*)d_in[4];
    const float* w2 = (const float*)d_in[5];
    const float* b2 = (const float*)d_in[6];
    float* out = (float*)d_out;

    cudaFuncSetAttribute(moe_gemm<1>, cudaFuncAttributeMaxDynamicSharedMemorySize, SMEM_SZ);
    cudaFuncSetAttribute(moe_gemm<2>, cudaFuncAttributeMaxDynamicSharedMemorySize, SMEM_SZ);

    void* ghp = nullptr;
    cudaGetSymbolAddress(&ghp, g_h);

    init_kernel<<<1, 32>>>();                       // 0
    router_kernel<<<NT/128, 128>>>(x, gw, gb);      // 1
    scanfill_kernel<<<1, 1024>>>();                 // 2
    dim3 g1(NF/128, 8, NE);
    moe_gemm<1><<<g1, 256, SMEM_SZ>>>(x, w1, b1);   // 3  <- ncu capture slot
    dim3 g2(NH/128, 8, NE*2);
    moe_gemm<2><<<g2, 256, SMEM_SZ>>>((const float*)ghp, w2, nullptr);  // 4
    combine_kernel<<<(NT*NH/4)/256, 256>>>(b2, out);                    // 5
}

// round 7
// speedup vs baseline: 1.0141x; 1.0141x over previous
#include <cuda_runtime.h>
#include <cstdint>
#include <math.h>

#define NT 1024
#define NH 1024
#define NF 4096
#define NE 8
#define NK 2

// ---- device scratch ----
__device__ int   g_sel [NT*NK];
__device__ float g_rw  [NT*NK];
__device__ int   g_slot[NT*NK];
__device__ int   g_cnt [NE];
__device__ int   g_off [NE];
__device__ int   g_tok [NT*NK];
__device__ float g_h[(size_t)(NT*NK)*NF];
__device__ float g_y[2][(size_t)(NT*NK)*NH];

// ---- helpers ----
__device__ __forceinline__ uint32_t smem_u32(const void* p){
    uint32_t a; asm("{ .reg .u64 t; cvta.to.shared.u64 t, %1; cvt.u32.u64 %0, t; }":"=r"(a):"l"(p)); return a;
}
__device__ __forceinline__ void cpa16(uint32_t s, const void* g){
    asm volatile("cp.async.cg.shared.global [%0], [%1], 16;"::"r"(s),"l"(g));
}
__device__ __forceinline__ void cpa_commit(){ asm volatile("cp.async.commit_group;"); }
template<int N> __device__ __forceinline__ void cpa_wait(){ asm volatile("cp.async.wait_group %0;"::"n"(N)); }
__device__ __forceinline__ uint32_t f2tf(float f){
    uint32_t r; asm("cvt.rna.tf32.f32 %0, %1;":"=r"(r):"f"(f)); return r;
}
// NOTE: non-volatile — register-only dataflow; lets ptxas interleave MMAs with
// the next kstep's shared loads instead of serializing on the asm fence.
__device__ __forceinline__ void mma8(float* d, const uint32_t* a, const uint32_t* b){
    asm("mma.sync.aligned.m16n8k8.row.col.f32.tf32.tf32.f32 "
        "{%0,%1,%2,%3}, {%4,%5,%6,%7}, {%8,%9}, {%0,%1,%2,%3};"
        : "+f"(d[0]),"+f"(d[1]),"+f"(d[2]),"+f"(d[3])
        : "r"(a[0]),"r"(a[1]),"r"(a[2]),"r"(a[3]),"r"(b[0]),"r"(b[1]));
}
__device__ __forceinline__ float gelu_exact(float v){
    return 0.5f * v * (1.0f + erff(v * 0.70710678118654752f));
}

// ---- aux kernels ----
__global__ void init_kernel(){
    int i = threadIdx.x;
    if (i < NE) g_cnt[i] = 0;
}

__global__ void router_kernel(const float* __restrict__ x,
                              const float* __restrict__ gw,
                              const float* __restrict__ gb){
    __shared__ float4 sg[NE*NH/4];
    int tid = threadIdx.x;
    for (int i = tid; i < NE*NH/4; i += blockDim.x) sg[i] = ((const float4*)gw)[i];
    __syncthreads();
    int t = blockIdx.x*blockDim.x + tid;
    const float4* xr = (const float4*)(x + (size_t)t*NH);
    float acc[NE];
#pragma unroll
    for (int e=0;e<NE;e++) acc[e] = gb[e];
    for (int i=0;i<NH/4;i++){
        float4 xv = xr[i];
#pragma unroll
        for (int e=0;e<NE;e++){
            float4 g = sg[e*(NH/4)+i];
            acc[e] += xv.x*g.x + xv.y*g.y + xv.z*g.z + xv.w*g.w;
        }
    }
    int i0=0; float l0=acc[0];
#pragma unroll
    for (int e=1;e<NE;e++) if (acc[e]>l0){ l0=acc[e]; i0=e; }
    int i1=-1; float l1=-3.4e38f;
#pragma unroll
    for (int e=0;e<NE;e++) if (e!=i0 && acc[e]>l1){ l1=acc[e]; i1=e; }
    float p0 = 1.0f/(1.0f+expf(l1-l0));
    g_sel[t*2+0]=i0; g_sel[t*2+1]=i1;
    g_rw [t*2+0]=p0; g_rw [t*2+1]=1.0f-p0;
    atomicAdd(&g_cnt[i0],1);
    atomicAdd(&g_cnt[i1],1);
}

__global__ void scanfill_kernel(){
    __shared__ int scur[NE];
    int tid = threadIdx.x;
    if (tid == 0){
        int o = 0;
        for (int e=0;e<NE;e++){ g_off[e]=o; scur[e]=0; o += g_cnt[e]; }
    }
    __syncthreads();
    for (int t = tid; t < NT; t += blockDim.x){
        for (int k=0;k<NK;k++){
            int e = g_sel[t*2+k];
            int pos = atomicAdd(&scur[e],1);
            int idx = g_off[e]+pos;
            g_tok[idx]    = t;
            g_slot[t*2+k] = idx;
        }
    }
}

// ---- grouped tf32 mma.sync GEMM ----
// CTA 128x128, BK=32, 256 thr = 8 warps (4m x 2n), warp tile 32x64, 2 CTAs/SM.
// 3-stage cp.async smem pipeline + FULL fragment double-buffer across ksteps.
// One __syncthreads per ktile. Non-volatile MMA asm for scheduling freedom.

#define ASTR 36
#define BSTR 132
#define STG_A (128*ASTR)
#define STG_B (32*BSTR)
#define STG_F (STG_A + STG_B)       // 8832 floats
#define NSTG  3
#define SMEM_SZ (NSTG*STG_F*4)      // 105984 bytes

template<int MODE>
__global__ __launch_bounds__(256, 2)
void moe_gemm(const float* __restrict__ Asrc,
              const float* __restrict__ W,
              const float* __restrict__ bias){
    const int z   = blockIdx.z;
    const int e   = (MODE==1) ? z : (z & 7);
    const int ks  = (MODE==1) ? 0 : (z >> 3);
    const int cnt = g_cnt[e];
    const int m0  = blockIdx.y * 128;
    if (m0 >= cnt) return;
    const int off = g_off[e];
    const int n0  = blockIdx.x * 128;
    const int ldB = (MODE==1) ? NF : NH;
    const int Kfull = (MODE==1) ? NH : NF;
    const int Kloc  = (MODE==1) ? NH : NF/2;
    const int k0    = (MODE==1) ? 0  : ks * (NF/2);
    const int KT    = Kloc / 32;

    extern __shared__ float smem[];
    const uint32_t sb = smem_u32(smem);
    const int tid = threadIdx.x, wid = tid>>5, lane = tid&31;
    const int g = lane>>2, tg = lane&3;
    const int wm = wid&3, wn = wid>>2;   // 4m x 2n, warp tile 32x64

    // A loads: thread -> row tid>>1, cols (tid&1)*16 + j*4
    const int arow_l = tid>>1;
    const int acol   = (tid&1)*16;
    int mi = m0 + arow_l;
    int ci = (mi < cnt) ? mi : (cnt-1);
    const float* aptr;
    if (MODE==1) aptr = Asrc + (size_t)g_tok[off+ci]*NH + acol;
    else         aptr = Asrc + (size_t)(off+ci)*NF + k0 + acol;

    // B loads: thread -> row tid>>3, cols (tid&7)*4 + j*32
    const int brow = tid>>3;
    const int bcol = (tid&7)*4;
    const float* bptr = W + (size_t)e*Kfull*ldB + (size_t)(k0 + brow)*ldB + n0 + bcol;

    const uint32_t adst = sb + ((uint32_t)(arow_l*ASTR + acol))*4u;
    const uint32_t bdst = sb + ((uint32_t)(STG_A + brow*BSTR + bcol))*4u;

    auto load_stage = [&](int s, int kt){
        uint32_t ab = adst + (uint32_t)s*STG_F*4u;
        uint32_t bb = bdst + (uint32_t)s*STG_F*4u;
        const float* ga  = aptr + kt*32;
        const float* gbp = bptr + (size_t)kt*32*ldB;
#pragma unroll
        for (int j=0;j<4;j++) cpa16(ab + j*16u, ga + j*4);
#pragma unroll
        for (int j=0;j<4;j++) cpa16(bb + j*128u, gbp + j*32);
    };

    load_stage(0,0); cpa_commit();
    load_stage(1,1); cpa_commit();

    float acc[2][8][4];
#pragma unroll
    for (int i=0;i<2;i++)
#pragma unroll
        for (int j=0;j<8;j++)
#pragma unroll
            for (int r=0;r<4;r++) acc[i][j][r] = 0.0f;

    uint32_t af[2][2][4], bf[2][8][2];

    auto load_frags = [&](const float* sA, const float* sB, int kstep, int buf){
#pragma unroll
        for (int i=0;i<2;i++){
            const float* pa = sA + (wm*32 + i*16 + g)*ASTR + kstep*8 + tg;
            af[buf][i][0] = f2tf(pa[0]);
            af[buf][i][1] = f2tf(pa[8*ASTR]);
            af[buf][i][2] = f2tf(pa[4]);
            af[buf][i][3] = f2tf(pa[8*ASTR+4]);
        }
#pragma unroll
        for (int j=0;j<8;j++){
            const float* pb = sB + (kstep*8 + tg)*BSTR + wn*64 + j*8 + g;
            bf[buf][j][0] = f2tf(pb[0]);
            bf[buf][j][1] = f2tf(pb[4*BSTR]);
        }
    };

    for (int kt = 0; kt < KT; kt++){
        cpa_wait<1>();
        __syncthreads();
        // all warps are past compute(kt-1); stage (kt+2)%3 == (kt-1)%3 is reusable
        if (kt + 2 < KT) load_stage((kt+2)%NSTG, kt+2);
        cpa_commit();

        const float* sA = smem + (kt%NSTG)*STG_F;
        const float* sB = sA + STG_A;
        load_frags(sA, sB, 0, 0);
#pragma unroll
        for (int kstep=0;kstep<4;kstep++){
            const int cur = kstep&1, nxt = cur^1;
            if (kstep < 3) load_frags(sA, sB, kstep+1, nxt);
#pragma unroll
            for (int i=0;i<2;i++)
#pragma unroll
                for (int j=0;j<8;j++)
                    mma8(acc[i][j], af[cur][i], bf[cur][j]);
        }
    }

    // ---- epilogue ----
    if (MODE == 1){
        const float* bp = bias + (size_t)e*NF + n0 + wn*64;
#pragma unroll
        for (int i=0;i<2;i++){
            int r0 = m0 + wm*32 + i*16 + g;
            int r1 = r0 + 8;
#pragma unroll
            for (int j=0;j<8;j++){
                int c = j*8 + tg*2;
                float b0 = __ldg(bp + c), b1v = __ldg(bp + c + 1);
                if (r0 < cnt){
                    float* o = g_h + (size_t)(off+r0)*NF + n0 + wn*64 + c;
                    float2 v; v.x = gelu_exact(acc[i][j][0] + b0);
                              v.y = gelu_exact(acc[i][j][1] + b1v);
                    *(float2*)o = v;
                }
                if (r1 < cnt){
                    float* o = g_h + (size_t)(off+r1)*NF + n0 + wn*64 + c;
                    float2 v; v.x = gelu_exact(acc[i][j][2] + b0);
                              v.y = gelu_exact(acc[i][j][3] + b1v);
                    *(float2*)o = v;
                }
            }
        }
    } else {
        float* Yb = g_y[ks];
#pragma unroll
        for (int i=0;i<2;i++){
            int r0 = m0 + wm*32 + i*16 + g;
            int r1 = r0 + 8;
#pragma unroll
            for (int j=0;j<8;j++){
                int c = n0 + wn*64 + j*8 + tg*2;
                if (r0 < cnt)
                    *(float2*)(Yb + (size_t)(off+r0)*NH + c) = make_float2(acc[i][j][0], acc[i][j][1]);
                if (r1 < cnt)
                    *(float2*)(Yb + (size_t)(off+r1)*NH + c) = make_float2(acc[i][j][2], acc[i][j][3]);
            }
        }
    }
}

// ---- combine ----
__global__ void combine_kernel(const float* __restrict__ b2, float* __restrict__ out){
    int idx = blockIdx.x*blockDim.x + threadIdx.x;
    int t  = idx >> 8;
    int h4 = (idx & 255) * 4;
    float4 a = make_float4(0.f,0.f,0.f,0.f);
#pragma unroll
    for (int k=0;k<2;k++){
        int e = g_sel[t*2+k];
        float w = g_rw[t*2+k];
        int sl = g_slot[t*2+k];
        float4 y0 = *(const float4*)&g_y[0][(size_t)sl*NH + h4];
        float4 y1 = *(const float4*)&g_y[1][(size_t)sl*NH + h4];
        float4 bb = *(const float4*)&b2[(size_t)e*NH + h4];
        a.x += w*(y0.x+y1.x+bb.x);
        a.y += w*(y0.y+y1.y+bb.y);
        a.z += w*(y0.z+y1.z+bb.z);
        a.w += w*(y0.w+y1.w+bb.w);
    }
    *(float4*)&out[(size_t)t*NH + h4] = a;
}

extern "C" void kernel_launch(void* const* d_in, const int* in_sizes, int n_in,
                              void* d_out, int out_size){
    const float* x  = (const float*)d_in[0];
    const float* gw = (const float*)d_in[1];
    const float* gb = (const float*)d_in[2];
    const float* w1 = (const float*)d_in[3];
    const float* b1 = (const float*)d_in[4];
    const float* w2 = (const float*)d_in[5];
    const float* b2 = (const float*)d_in[6];
    float* out = (float*)d_out;

    cudaFuncSetAttribute(moe_gemm<1>, cudaFuncAttributeMaxDynamicSharedMemorySize, SMEM_SZ);
    cudaFuncSetAttribute(moe_gemm<2>, cudaFuncAttributeMaxDynamicSharedMemorySize, SMEM_SZ);

    void* ghp = nullptr;
    cudaGetSymbolAddress(&ghp, g_h);

    init_kernel<<<1, 32>>>();                       // 0
    router_kernel<<<NT/128, 128>>>(x, gw, gb);      // 1
    scanfill_kernel<<<1, 1024>>>();                 // 2
    dim3 g1(NF/128, 8, NE);
    moe_gemm<1><<<g1, 256, SMEM_SZ>>>(x, w1, b1);   // 3  <- ncu capture slot
    dim3 g2(NH/128, 8, NE*2);
    moe_gemm<2><<<g2, 256, SMEM_SZ>>>((const float*)ghp, w2, nullptr);  // 4
    combine_kernel<<<(NT*NH/4)/256, 256>>>(b2, out);                    // 5
}

// round 10
// speedup vs baseline: 1.0867x; 1.0716x over previous
#include <cuda_runtime.h>
#include <cstdint>
#include <math.h>

#define NT 1024
#define NH 1024
#define NF 4096
#define NE 8
#define NK 2
#define NSPL 4   // gemm2 split-K

// ---- device scratch ----
__device__ int   g_sel [NT*NK];
__device__ float g_rw  [NT*NK];
__device__ int   g_slot[NT*NK];
__device__ int   g_cnt [NE];
__device__ int   g_off [NE];
__device__ int   g_tok [NT*NK];
__device__ float g_xc[(size_t)NT*NH];              // tf32-rounded x
__device__ float g_h[(size_t)(NT*NK)*NF];          // tf32-rounded gelu acts
__device__ float g_y[NSPL][(size_t)(NT*NK)*NH];    // gemm2 split-K partials

// ---- helpers ----
__device__ __forceinline__ uint32_t smem_u32(const void* p){
    uint32_t a; asm("{ .reg .u64 t; cvta.to.shared.u64 t, %1; cvt.u32.u64 %0, t; }":"=r"(a):"l"(p)); return a;
}
__device__ __forceinline__ void cpa16(uint32_t s, const void* g){
    asm volatile("cp.async.cg.shared.global [%0], [%1], 16;"::"r"(s),"l"(g));
}
__device__ __forceinline__ void cpa_commit(){ asm volatile("cp.async.commit_group;"); }
template<int N> __device__ __forceinline__ void cpa_wait(){ asm volatile("cp.async.wait_group %0;"::"n"(N)); }
__device__ __forceinline__ uint32_t f2tf(float f){
    uint32_t r; asm("cvt.rna.tf32.f32 %0, %1;":"=r"(r):"f"(f)); return r;
}
__device__ __forceinline__ float f2tf_f(float f){
    uint32_t r = f2tf(f); return __uint_as_float(r);
}
// ldmatrix x4: one instruction = full tf32 m16n8k8 A-fragment (4 regs)
__device__ __forceinline__ void ldmA(uint32_t* r, uint32_t addr){
    asm("ldmatrix.sync.aligned.m8n8.x4.shared.b16 {%0,%1,%2,%3}, [%4];"
        : "=r"(r[0]),"=r"(r[1]),"=r"(r[2]),"=r"(r[3]) : "r"(addr) : "memory");
}
// non-volatile mma: register dataflow only, ptxas free to schedule
__device__ __forceinline__ void mma8(float* d, const uint32_t* a, const uint32_t* b){
    asm("mma.sync.aligned.m16n8k8.row.col.f32.tf32.tf32.f32 "
        "{%0,%1,%2,%3}, {%4,%5,%6,%7}, {%8,%9}, {%0,%1,%2,%3};"
        : "+f"(d[0]),"+f"(d[1]),"+f"(d[2]),"+f"(d[3])
        : "r"(a[0]),"r"(a[1]),"r"(a[2]),"r"(a[3]),"r"(b[0]),"r"(b[1]));
}
__device__ __forceinline__ float gelu_exact(float v){
    return 0.5f * v * (1.0f + erff(v * 0.70710678118654752f));
}

// ---- aux kernels ----
__global__ void init_kernel(){
    int i = threadIdx.x;
    if (i < NE) g_cnt[i] = 0;
}

// router + write tf32-rounded copy of x
__global__ void router_kernel(const float* __restrict__ x,
                              const float* __restrict__ gw,
                              const float* __restrict__ gb){
    __shared__ float4 sg[NE*NH/4];
    int tid = threadIdx.x;
    for (int i = tid; i < NE*NH/4; i += blockDim.x) sg[i] = ((const float4*)gw)[i];
    __syncthreads();
    int t = blockIdx.x*blockDim.x + tid;
    const float4* xr = (const float4*)(x + (size_t)t*NH);
    float4* xc = (float4*)(g_xc + (size_t)t*NH);
    float acc[NE];
#pragma unroll
    for (int e=0;e<NE;e++) acc[e] = gb[e];
    for (int i=0;i<NH/4;i++){
        float4 xv = xr[i];
        float4 cv;
        cv.x = f2tf_f(xv.x); cv.y = f2tf_f(xv.y);
        cv.z = f2tf_f(xv.z); cv.w = f2tf_f(xv.w);
        xc[i] = cv;
#pragma unroll
        for (int e=0;e<NE;e++){
            float4 g = sg[e*(NH/4)+i];
            acc[e] += xv.x*g.x + xv.y*g.y + xv.z*g.z + xv.w*g.w;
        }
    }
    int i0=0; float l0=acc[0];
#pragma unroll
    for (int e=1;e<NE;e++) if (acc[e]>l0){ l0=acc[e]; i0=e; }
    int i1=-1; float l1=-3.4e38f;
#pragma unroll
    for (int e=0;e<NE;e++) if (e!=i0 && acc[e]>l1){ l1=acc[e]; i1=e; }
    float p0 = 1.0f/(1.0f+expf(l1-l0));
    g_sel[t*2+0]=i0; g_sel[t*2+1]=i1;
    g_rw [t*2+0]=p0; g_rw [t*2+1]=1.0f-p0;
    atomicAdd(&g_cnt[i0],1);
    atomicAdd(&g_cnt[i1],1);
}

__global__ void scanfill_kernel(){
    __shared__ int scur[NE];
    int tid = threadIdx.x;
    if (tid == 0){
        int o = 0;
        for (int e=0;e<NE;e++){ g_off[e]=o; scur[e]=0; o += g_cnt[e]; }
    }
    __syncthreads();
    for (int t = tid; t < NT; t += blockDim.x){
        for (int k=0;k<NK;k++){
            int e = g_sel[t*2+k];
            int pos = atomicAdd(&scur[e],1);
            int idx = g_off[e]+pos;
            g_tok[idx]    = t;
            g_slot[t*2+k] = idx;
        }
    }
}

// ---- grouped tf32 mma.sync GEMM ----
// CTA 128x128, BK=32, 256 thr = 8 warps (4m x 2n), warp 32x64, 2 CTAs/SM.
// A-frags: 1 ldmatrix.x4 per 16x8 tile (A pre-rounded to tf32 in global).
// B-frags: LDS.32, BSTR=136 -> conflict-free. No CVT in inner loop (B HW-truncated).

#define ASTR 36
#define BSTR 136
#define STG_A (128*ASTR)            // 4608 floats
#define STG_B (32*BSTR)             // 4352 floats
#define STG_F (STG_A + STG_B)       // 8960 floats
#define NSTG  3
#define SMEM_SZ (NSTG*STG_F*4)      // 107520 bytes

template<int MODE>
__global__ __launch_bounds__(256, 2)
void moe_gemm(const float* __restrict__ Asrc,
              const float* __restrict__ W,
              const float* __restrict__ bias){
    const int z   = blockIdx.z;
    const int e   = (MODE==1) ? z : (z & 7);
    const int ks  = (MODE==1) ? 0 : (z >> 3);
    const int cnt = g_cnt[e];
    const int m0  = blockIdx.y * 128;
    if (m0 >= cnt) return;
    const int off = g_off[e];
    const int n0  = blockIdx.x * 128;
    const int ldB = (MODE==1) ? NF : NH;
    const int Kfull = (MODE==1) ? NH : NF;
    const int Kloc  = (MODE==1) ? NH : NF/NSPL;
    const int k0    = (MODE==1) ? 0  : ks * (NF/NSPL);
    const int KT    = Kloc / 32;

    extern __shared__ float smem[];
    const uint32_t sb = smem_u32(smem);
    const int tid = threadIdx.x, wid = tid>>5, lane = tid&31;
    const int g = lane>>2, tg = lane&3;
    const int wm = wid&3, wn = wid>>2;   // 4m x 2n, warp tile 32x64

    // A loads: thread -> row tid>>1, cols (tid&1)*16 + j*4
    const int arow_l = tid>>1;
    const int acol   = (tid&1)*16;
    int mi = m0 + arow_l;
    int ci = (mi < cnt) ? mi : (cnt-1);
    const float* aptr;
    if (MODE==1) aptr = Asrc + (size_t)g_tok[off+ci]*NH + acol;
    else         aptr = Asrc + (size_t)(off+ci)*NF + k0 + acol;

    // B loads: thread -> row tid>>3, cols (tid&7)*4 + j*32
    const int brow = tid>>3;
    const int bcol = (tid&7)*4;
    const float* bptr = W + (size_t)e*Kfull*ldB + (size_t)(k0 + brow)*ldB + n0 + bcol;

    const uint32_t adst = sb + ((uint32_t)(arow_l*ASTR + acol))*4u;
    const uint32_t bdst = sb + ((uint32_t)(STG_A + brow*BSTR + bcol))*4u;

    auto load_stage = [&](int s, int kt){
        uint32_t ab = adst + (uint32_t)s*STG_F*4u;
        uint32_t bb = bdst + (uint32_t)s*STG_F*4u;
        const float* ga  = aptr + kt*32;
        const float* gbp = bptr + (size_t)kt*32*ldB;
#pragma unroll
        for (int j=0;j<4;j++) cpa16(ab + j*16u, ga + j*4);
#pragma unroll
        for (int j=0;j<4;j++) cpa16(bb + j*128u, gbp + j*32);
    };

    load_stage(0,0); cpa_commit();
    load_stage(1,1); cpa_commit();

    // per-lane ldmatrix base addresses for the 2 A i-tiles (within stage 0)
    // lane l -> row = l&15 of tile, f32-colgroup = (l>>4)*4
    uint32_t a_lm[2];
#pragma unroll
    for (int i=0;i<2;i++)
        a_lm[i] = sb + ((uint32_t)((wm*32 + i*16 + (lane&15))*ASTR + (lane>>4)*4))*4u;

    float acc[2][8][4];
#pragma unroll
    for (int i=0;i<2;i++)
#pragma unroll
        for (int j=0;j<8;j++)
#pragma unroll
            for (int r=0;r<4;r++) acc[i][j][r] = 0.0f;

    for (int kt = 0; kt < KT; kt++){
        cpa_wait<1>();
        __syncthreads();
        if (kt + 2 < KT) load_stage((kt+2)%NSTG, kt+2);
        cpa_commit();

        const uint32_t stoff = (uint32_t)(kt%NSTG)*STG_F*4u;
        const float* sB = smem + (kt%NSTG)*STG_F + STG_A;
#pragma unroll
        for (int kstep=0;kstep<4;kstep++){
            uint32_t af[2][4];
#pragma unroll
            for (int i=0;i<2;i++)
                ldmA(af[i], a_lm[i] + stoff + kstep*32u);
            uint32_t bf[8][2];
#pragma unroll
            for (int j=0;j<8;j++){
                const float* pb = sB + (kstep*8 + tg)*BSTR + wn*64 + j*8 + g;
                bf[j][0] = __float_as_uint(pb[0]);
                bf[j][1] = __float_as_uint(pb[4*BSTR]);
            }
#pragma unroll
            for (int i=0;i<2;i++)
#pragma unroll
                for (int j=0;j<8;j++)
                    mma8(acc[i][j], af[i], bf[j]);
        }
        __syncthreads();
    }

    // ---- epilogue ----
    if (MODE == 1){
        const float* bp = bias + (size_t)e*NF + n0 + wn*64;
#pragma unroll
        for (int i=0;i<2;i++){
            int r0 = m0 + wm*32 + i*16 + g;
            int r1 = r0 + 8;
#pragma unroll
            for (int j=0;j<8;j++){
                int c = j*8 + tg*2;
                float b0 = __ldg(bp + c), b1v = __ldg(bp + c + 1);
                if (r0 < cnt){
                    float* o = g_h + (size_t)(off+r0)*NF + n0 + wn*64 + c;
                    float2 v; v.x = f2tf_f(gelu_exact(acc[i][j][0] + b0));
                              v.y = f2tf_f(gelu_exact(acc[i][j][1] + b1v));
                    *(float2*)o = v;
                }
                if (r1 < cnt){
                    float* o = g_h + (size_t)(off+r1)*NF + n0 + wn*64 + c;
                    float2 v; v.x = f2tf_f(gelu_exact(acc[i][j][2] + b0));
                              v.y = f2tf_f(gelu_exact(acc[i][j][3] + b1v));
                    *(float2*)o = v;
                }
            }
        }
    } else {
        float* Yb = g_y[ks];
#pragma unroll
        for (int i=0;i<2;i++){
            int r0 = m0 + wm*32 + i*16 + g;
            int r1 = r0 + 8;
#pragma unroll
            for (int j=0;j<8;j++){
                int c = n0 + wn*64 + j*8 + tg*2;
                if (r0 < cnt)
                    *(float2*)(Yb + (size_t)(off+r0)*NH + c) = make_float2(acc[i][j][0], acc[i][j][1]);
                if (r1 < cnt)
                    *(float2*)(Yb + (size_t)(off+r1)*NH + c) = make_float2(acc[i][j][2], acc[i][j][3]);
            }
        }
    }
}

// ---- combine: out[t] = sum_k rw_k * ( sum_p g_y[p][slot_k] + b2[e_k] ) ----
__global__ void combine_kernel(const float* __restrict__ b2, float* __restrict__ out){
    int idx = blockIdx.x*blockDim.x + threadIdx.x;
    int t  = idx >> 8;
    int h4 = (idx & 255) * 4;
    float4 a = make_float4(0.f,0.f,0.f,0.f);
#pragma unroll
    for (int k=0;k<2;k++){
        int e = g_sel[t*2+k];
        float w = g_rw[t*2+k];
        int sl = g_slot[t*2+k];
        float4 s = *(const float4*)&b2[(size_t)e*NH + h4];
#pragma unroll
        for (int p=0;p<NSPL;p++){
            float4 y = *(const float4*)&g_y[p][(size_t)sl*NH + h4];
            s.x += y.x; s.y += y.y; s.z += y.z; s.w += y.w;
        }
        a.x += w*s.x; a.y += w*s.y; a.z += w*s.z; a.w += w*s.w;
    }
    *(float4*)&out[(size_t)t*NH + h4] = a;
}

extern "C" void kernel_launch(void* const* d_in, const int* in_sizes, int n_in,
                              void* d_out, int out_size){
    const float* x  = (const float*)d_in[0];
    const float* gw = (const float*)d_in[1];
    const float* gb = (const float*)d_in[2];
    const float* w1 = (const float*)d_in[3];
    const float* b1 = (const float*)d_in[4];
    const float* w2 = (const float*)d_in[5];
    const float* b2 = (const float*)d_in[6];
    float* out = (float*)d_out;

    cudaFuncSetAttribute(moe_gemm<1>, cudaFuncAttributeMaxDynamicSharedMemorySize, SMEM_SZ);
    cudaFuncSetAttribute(moe_gemm<2>, cudaFuncAttributeMaxDynamicSharedMemorySize, SMEM_SZ);

    void *gxp = nullptr, *ghp = nullptr;
    cudaGetSymbolAddress(&gxp, g_xc);
    cudaGetSymbolAddress(&ghp, g_h);

    init_kernel<<<1, 32>>>();                       // 0
    router_kernel<<<NT/128, 128>>>(x, gw, gb);      // 1
    scanfill_kernel<<<1, 1024>>>();                 // 2
    dim3 g1(NF/128, 8, NE);
    moe_gemm<1><<<g1, 256, SMEM_SZ>>>((const float*)gxp, w1, b1);  // 3 <- ncu slot
    dim3 g2(NH/128, 8, NE*NSPL);
    moe_gemm<2><<<g2, 256, SMEM_SZ>>>((const float*)ghp, w2, nullptr);  // 4
    combine_kernel<<<(NT*NH/4)/256, 256>>>(b2, out);                    // 5
}

// round 11
// speedup vs baseline: 1.3233x; 1.2177x over previous
#include <cuda_runtime.h>
#include <cuda_fp16.h>
#include <cstdint>
#include <math.h>

#define NT 1024
#define NH 1024
#define NF 4096
#define NE 8
#define NK 2
#define NSPL 4   // gemm2 split-K

// ---- device scratch ----
__device__ int    g_sel [NT*NK];
__device__ float  g_rw  [NT*NK];
__device__ int    g_slot[NT*NK];
__device__ int    g_cnt [NE];
__device__ int    g_off [NE];
__device__ int    g_tok [NT*NK];
__device__ __half g_xh[(size_t)NT*NH];               // fp16 x
__device__ __half g_w1h[(size_t)NE*NH*NF];           // fp16 w1 (67 MB)
__device__ __half g_w2h[(size_t)NE*NF*NH];           // fp16 w2 (67 MB)
__device__ __half g_hh[(size_t)(NT*NK)*NF];          // fp16 gelu acts
__device__ float  g_y[NSPL][(size_t)(NT*NK)*NH];     // gemm2 split-K partials

// ---- helpers ----
__device__ __forceinline__ uint32_t smem_u32(const void* p){
    uint32_t a; asm("{ .reg .u64 t; cvta.to.shared.u64 t, %1; cvt.u32.u64 %0, t; }":"=r"(a):"l"(p)); return a;
}
__device__ __forceinline__ void cpa16(uint32_t s, const void* g){
    asm volatile("cp.async.cg.shared.global [%0], [%1], 16;"::"r"(s),"l"(g));
}
__device__ __forceinline__ void cpa_commit(){ asm volatile("cp.async.commit_group;"); }
template<int N> __device__ __forceinline__ void cpa_wait(){ asm volatile("cp.async.wait_group %0;"::"n"(N)); }
__device__ __forceinline__ void ldmx4(uint32_t* r, uint32_t a){
    asm("ldmatrix.sync.aligned.m8n8.x4.shared.b16 {%0,%1,%2,%3}, [%4];"
        : "=r"(r[0]),"=r"(r[1]),"=r"(r[2]),"=r"(r[3]) : "r"(a) : "memory");
}
__device__ __forceinline__ void ldmx4t(uint32_t* r, uint32_t a){
    asm("ldmatrix.sync.aligned.m8n8.x4.trans.shared.b16 {%0,%1,%2,%3}, [%4];"
        : "=r"(r[0]),"=r"(r[1]),"=r"(r[2]),"=r"(r[3]) : "r"(a) : "memory");
}
// fp16 HMMA, fp32 accum; non-volatile for scheduling freedom
__device__ __forceinline__ void mma16(float* d, const uint32_t* a, const uint32_t* b){
    asm("mma.sync.aligned.m16n8k16.row.col.f32.f16.f16.f32 "
        "{%0,%1,%2,%3}, {%4,%5,%6,%7}, {%8,%9}, {%0,%1,%2,%3};"
        : "+f"(d[0]),"+f"(d[1]),"+f"(d[2]),"+f"(d[3])
        : "r"(a[0]),"r"(a[1]),"r"(a[2]),"r"(a[3]),"r"(b[0]),"r"(b[1]));
}
__device__ __forceinline__ float gelu_exact(float v){
    return 0.5f * v * (1.0f + erff(v * 0.70710678118654752f));
}

// ---- weight conversion: fp32 -> fp16 (one launch, both w1 and w2) ----
__global__ void convert_w(const float* __restrict__ w1, const float* __restrict__ w2){
    const size_t N1 = (size_t)NE*NH*NF;
    size_t i = ((size_t)blockIdx.x*blockDim.x + threadIdx.x) * 8;
    const float* src; __half* dst;
    if (i < N1){ src = w1 + i;        dst = g_w1h + i; }
    else       { src = w2 + (i - N1); dst = g_w2h + (i - N1); }
    float4 v0 = *(const float4*)src;
    float4 v1 = *(const float4*)(src + 4);
    __half2* d2 = (__half2*)dst;
    d2[0] = __floats2half2_rn(v0.x, v0.y);
    d2[1] = __floats2half2_rn(v0.z, v0.w);
    d2[2] = __floats2half2_rn(v1.x, v1.y);
    d2[3] = __floats2half2_rn(v1.z, v1.w);
}

// ---- router: fp32 gating + fp16 copy of x ----
__global__ void router_kernel(const float* __restrict__ x,
                              const float* __restrict__ gw,
                              const float* __restrict__ gb){
    __shared__ float4 sg[NE*NH/4];
    int tid = threadIdx.x;
    for (int i = tid; i < NE*NH/4; i += blockDim.x) sg[i] = ((const float4*)gw)[i];
    __syncthreads();
    int t = blockIdx.x*blockDim.x + tid;
    const float4* xr = (const float4*)(x + (size_t)t*NH);
    __half2* xc = (__half2*)(g_xh + (size_t)t*NH);
    float acc[NE];
#pragma unroll
    for (int e=0;e<NE;e++) acc[e] = gb[e];
    for (int i=0;i<NH/4;i++){
        float4 xv = xr[i];
        xc[i*2+0] = __floats2half2_rn(xv.x, xv.y);
        xc[i*2+1] = __floats2half2_rn(xv.z, xv.w);
#pragma unroll
        for (int e=0;e<NE;e++){
            float4 g = sg[e*(NH/4)+i];
            acc[e] += xv.x*g.x + xv.y*g.y + xv.z*g.z + xv.w*g.w;
        }
    }
    int i0=0; float l0=acc[0];
#pragma unroll
    for (int e=1;e<NE;e++) if (acc[e]>l0){ l0=acc[e]; i0=e; }
    int i1=-1; float l1=-3.4e38f;
#pragma unroll
    for (int e=0;e<NE;e++) if (e!=i0 && acc[e]>l1){ l1=acc[e]; i1=e; }
    float p0 = 1.0f/(1.0f+expf(l1-l0));
    g_sel[t*2+0]=i0; g_sel[t*2+1]=i1;
    g_rw [t*2+0]=p0; g_rw [t*2+1]=1.0f-p0;
}

// ---- single block: count, scan, scatter (no separate init needed) ----
__global__ void scanfill_kernel(){
    __shared__ int scnt[NE], scur[NE];
    int tid = threadIdx.x;   // 1024 threads, 1 token each
    if (tid < NE){ scnt[tid] = 0; scur[tid] = 0; }
    __syncthreads();
    int e0 = g_sel[tid*2+0], e1 = g_sel[tid*2+1];
    atomicAdd(&scnt[e0],1);
    atomicAdd(&scnt[e1],1);
    __syncthreads();
    if (tid == 0){
        int o = 0;
        for (int e=0;e<NE;e++){ g_off[e]=o; g_cnt[e]=scnt[e]; o += scnt[e]; }
    }
    __syncthreads();
#pragma unroll
    for (int k=0;k<NK;k++){
        int e = g_sel[tid*2+k];
        int pos = atomicAdd(&scur[e],1);
        int idx = g_off[e]+pos;
        g_tok[idx]     = tid;
        g_slot[tid*2+k]= idx;
    }
}

// ---- grouped fp16 mma.sync GEMM ----
// CTA 128x128, BK=64 (halves), 256 thr = 8 warps (4m x 2n), warp 32x64, 2 CTAs/SM.
// A-frags: ldmatrix.x4 (2/kstep); B-frags: ldmatrix.x4.trans (4/kstep).
// mma.m16n8k16.f32.f16.f16.f32, 16 MMA/kstep/warp, 4 ksteps/ktile.

#define ASTR 72      // halves per A row (64 + 8 pad)
#define BSTR 136     // halves per B row (128 + 8 pad)
#define STG_AH (128*ASTR)          // 9216 halves
#define STG_BH (64*BSTR)           // 8704 halves
#define STG_H  (STG_AH + STG_BH)   // 17920 halves
#define NSTG 3
#define SMEM_SZ (NSTG*STG_H*2)     // 107520 bytes

template<int MODE>
__global__ __launch_bounds__(256, 2)
void moe_gemm(const __half* __restrict__ Asrc,
              const __half* __restrict__ W,
              const float* __restrict__ bias){
    const int z   = blockIdx.z;
    const int e   = (MODE==1) ? z : (z & 7);
    const int ks  = (MODE==1) ? 0 : (z >> 3);
    const int cnt = g_cnt[e];
    const int m0  = blockIdx.y * 128;
    if (m0 >= cnt) return;
    const int off = g_off[e];
    const int n0  = blockIdx.x * 128;
    const int ldB = (MODE==1) ? NF : NH;
    const int Kfull = (MODE==1) ? NH : NF;
    const int Kloc  = (MODE==1) ? NH : NF/NSPL;
    const int k0    = (MODE==1) ? 0  : ks * (NF/NSPL);
    const int KT    = Kloc / 64;

    extern __shared__ __half smem[];
    const uint32_t sb = smem_u32(smem);
    const int tid = threadIdx.x, wid = tid>>5, lane = tid&31;
    const int g = lane>>2, tg = lane&3;
    const int wm = wid&3, wn = wid>>2;   // 4m x 2n, warp tile 32x64

    // A cp.async: thread -> row tid>>1, halves (tid&1)*32 + j*8 (j=0..3)
    const int arow = tid>>1;
    const int acolh = (tid&1)*32;
    int mi = m0 + arow;
    int ci = (mi < cnt) ? mi : (cnt-1);
    const __half* aptr;
    if (MODE==1) aptr = Asrc + (size_t)g_tok[off+ci]*NH + acolh;
    else         aptr = Asrc + (size_t)(off+ci)*NF + k0 + acolh;

    // B cp.async: thread -> k-row tid>>2, halves (tid&3)*32 + j*8
    const int brow = tid>>2;
    const int bcolh = (tid&3)*32;
    const __half* bptr = W + (size_t)e*Kfull*ldB + (size_t)(k0 + brow)*ldB + n0 + bcolh;

    const uint32_t adst = sb + (uint32_t)(arow*ASTR + acolh)*2u;
    const uint32_t bdst = sb + (uint32_t)(STG_AH + brow*BSTR + bcolh)*2u;

    auto load_stage = [&](int s, int kt){
        uint32_t ab = adst + (uint32_t)s*STG_H*2u;
        uint32_t bb = bdst + (uint32_t)s*STG_H*2u;
        const __half* ga  = aptr + kt*64;
        const __half* gbp = bptr + (size_t)kt*64*ldB;
#pragma unroll
        for (int j=0;j<4;j++) cpa16(ab + j*16u, ga + j*8);
#pragma unroll
        for (int j=0;j<4;j++) cpa16(bb + j*16u, gbp + j*8);
    };

    load_stage(0,0); cpa_commit();
    load_stage(1,1); cpa_commit();

    // ldmatrix lane bases
    uint32_t a_lm[2], b_lm[4];
#pragma unroll
    for (int i=0;i<2;i++)
        a_lm[i] = sb + (uint32_t)((wm*32 + i*16 + (lane&15))*ASTR + (lane>>4)*8)*2u;
#pragma unroll
    for (int jj=0;jj<4;jj++)
        b_lm[jj] = sb + (uint32_t)(STG_AH + (lane&15)*BSTR + wn*64 + jj*16 + (lane>>4)*8)*2u;

    float acc[2][8][4];
#pragma unroll
    for (int i=0;i<2;i++)
#pragma unroll
        for (int j=0;j<8;j++)
#pragma unroll
            for (int r=0;r<4;r++) acc[i][j][r] = 0.0f;

    for (int kt = 0; kt < KT; kt++){
        cpa_wait<1>();
        __syncthreads();
        // all warps finished compute(kt-1); stage (kt+2)%3 == (kt-1)%3 reusable
        if (kt + 2 < KT) load_stage((kt+2)%NSTG, kt+2);
        cpa_commit();

        const uint32_t stoff = (uint32_t)(kt%NSTG)*STG_H*2u;
#pragma unroll
        for (int kstep=0;kstep<4;kstep++){
            uint32_t af[2][4];
#pragma unroll
            for (int i=0;i<2;i++)
                ldmx4(af[i], a_lm[i] + stoff + (uint32_t)kstep*32u);
            uint32_t bf[4][4];
#pragma unroll
            for (int jj=0;jj<4;jj++)
                ldmx4t(bf[jj], b_lm[jj] + stoff + (uint32_t)kstep*(16u*BSTR*2u));
#pragma unroll
            for (int i=0;i<2;i++)
#pragma unroll
                for (int jj=0;jj<4;jj++){
                    mma16(acc[i][jj*2+0], af[i], &bf[jj][0]);
                    mma16(acc[i][jj*2+1], af[i], &bf[jj][2]);
                }
        }
    }

    // ---- epilogue ----
    if (MODE == 1){
        const float* bp = bias + (size_t)e*NF + n0 + wn*64;
#pragma unroll
        for (int i=0;i<2;i++){
            int r0 = m0 + wm*32 + i*16 + g;
            int r1 = r0 + 8;
#pragma unroll
            for (int j=0;j<8;j++){
                int c = j*8 + tg*2;
                float b0 = __ldg(bp + c), b1v = __ldg(bp + c + 1);
                if (r0 < cnt){
                    __half2* o = (__half2*)(g_hh + (size_t)(off+r0)*NF + n0 + wn*64 + c);
                    *o = __floats2half2_rn(gelu_exact(acc[i][j][0] + b0),
                                           gelu_exact(acc[i][j][1] + b1v));
                }
                if (r1 < cnt){
                    __half2* o = (__half2*)(g_hh + (size_t)(off+r1)*NF + n0 + wn*64 + c);
                    *o = __floats2half2_rn(gelu_exact(acc[i][j][2] + b0),
                                           gelu_exact(acc[i][j][3] + b1v));
                }
            }
        }
    } else {
        float* Yb = g_y[ks];
#pragma unroll
        for (int i=0;i<2;i++){
            int r0 = m0 + wm*32 + i*16 + g;
            int r1 = r0 + 8;
#pragma unroll
            for (int j=0;j<8;j++){
                int c = n0 + wn*64 + j*8 + tg*2;
                if (r0 < cnt)
                    *(float2*)(Yb + (size_t)(off+r0)*NH + c) = make_float2(acc[i][j][0], acc[i][j][1]);
                if (r1 < cnt)
                    *(float2*)(Yb + (size_t)(off+r1)*NH + c) = make_float2(acc[i][j][2], acc[i][j][3]);
            }
        }
    }
}

// ---- combine: out[t] = sum_k rw_k * ( sum_p g_y[p][slot_k] + b2[e_k] ) ----
__global__ void combine_kernel(const float* __restrict__ b2, float* __restrict__ out){
    int idx = blockIdx.x*blockDim.x + threadIdx.x;
    int t  = idx >> 8;
    int h4 = (idx & 255) * 4;
    float4 a = make_float4(0.f,0.f,0.f,0.f);
#pragma unroll
    for (int k=0;k<2;k++){
        int e = g_sel[t*2+k];
        float w = g_rw[t*2+k];
        int sl = g_slot[t*2+k];
        float4 s = *(const float4*)&b2[(size_t)e*NH + h4];
#pragma unroll
        for (int p=0;p<NSPL;p++){
            float4 y = *(const float4*)&g_y[p][(size_t)sl*NH + h4];
            s.x += y.x; s.y += y.y; s.z += y.z; s.w += y.w;
        }
        a.x += w*s.x; a.y += w*s.y; a.z += w*s.z; a.w += w*s.w;
    }
    *(float4*)&out[(size_t)t*NH + h4] = a;
}

extern "C" void kernel_launch(void* const* d_in, const int* in_sizes, int n_in,
                              void* d_out, int out_size){
    const float* x  = (const float*)d_in[0];
    const float* gw = (const float*)d_in[1];
    const float* gb = (const float*)d_in[2];
    const float* w1 = (const float*)d_in[3];
    const float* b1 = (const float*)d_in[4];
    const float* w2 = (const float*)d_in[5];
    const float* b2 = (const float*)d_in[6];
    float* out = (float*)d_out;

    cudaFuncSetAttribute(moe_gemm<1>, cudaFuncAttributeMaxDynamicSharedMemorySize, SMEM_SZ);
    cudaFuncSetAttribute(moe_gemm<2>, cudaFuncAttributeMaxDynamicSharedMemorySize, SMEM_SZ);

    void *gxp = nullptr, *ghp = nullptr, *gw1p = nullptr, *gw2p = nullptr;
    cudaGetSymbolAddress(&gxp,  g_xh);
    cudaGetSymbolAddress(&ghp,  g_hh);
    cudaGetSymbolAddress(&gw1p, g_w1h);
    cudaGetSymbolAddress(&gw2p, g_w2h);

    router_kernel<<<NT/128, 128>>>(x, gw, gb);                     // 0
    scanfill_kernel<<<1, 1024>>>();                                // 1
    // 2*33.55M halves / 8 per thread = 8.39M threads
    convert_w<<<(2*NE*NH*NF/8)/256, 256>>>(w1, w2);                // 2
    dim3 g1(NF/128, 8, NE);
    moe_gemm<1><<<g1, 256, SMEM_SZ>>>((const __half*)gxp, w1 ? (const __half*)gw1p : nullptr, b1);  // 3 <- ncu slot
    dim3 g2(NH/128, 8, NE*NSPL);
    moe_gemm<2><<<g2, 256, SMEM_SZ>>>((const __half*)ghp, (const __half*)gw2p, nullptr);            // 4
    combine_kernel<<<(NT*NH/4)/256, 256>>>(b2, out);                                                // 5
}